// round 1
// baseline (speedup 1.0000x reference)
#include <cuda_runtime.h>
#include <cuda_bf16.h>
#include <cstddef>

// Problem constants
// B=32, T=32768, K=N=8, D=256
// EPS=0.1, PW=5, GAMMA=2, ALPHA=0.25, MARGIN=0.5
// weights: exist 1.0, ortho 0.1, contr 0.1, overlap 0.5

#define FULLMASK 0xffffffffu

// Global scratch: per-batch 144 floats:
//   [0..63]   A[k][n]   = sum_t ((PW-1)*nlp - x) * y
//   [64..127] W[k][n]   = sum_t p^2 * x * y
//   [128..135] S1[k]    = sum_t (nlp + x)
//   [136..143] S2[k]    = sum_t p^2*(nlp + 0.9x)
// scalars at 4608+: [0]=overlapSum [1]=assignSum [2]=orthoSum [3]=contrSum
__device__ float gBuf[32 * 144 + 8];

__global__ void zero_kernel() {
    int i = blockIdx.x * blockDim.x + threadIdx.x;
    const int n = 32 * 144 + 8;
    for (; i < n; i += gridDim.x * blockDim.x) gBuf[i] = 0.f;
}

__device__ __forceinline__ void proc(float x, const float* yv,
                                     float* A, float* W, float& s1, float& s2) {
    x = (x == x) ? x : 0.f;                 // nan_to_num(logits)
    float ax  = fabsf(x);
    float e   = __expf(-ax);
    float l   = __logf(1.f + e);
    float nlp = l + fmaxf(-x, 0.f);         // softplus(-x) = -log sigmoid(x)
    float p2  = __expf(-2.f * nlp);         // sigmoid(x)^2
    float u   = fmaf(4.f, nlp, -x);         // (PW-1)*nlp - x
    float w   = p2 * x;
    s1 += nlp + x;
    s2  = fmaf(p2, fmaf(0.9f, x, nlp), s2);
#pragma unroll
    for (int n = 0; n < 8; n++) {
        A[n] = fmaf(yv[n], u, A[n]);
        W[n] = fmaf(yv[n], w, W[n]);
    }
}

__global__ void __launch_bounds__(256)
main_kernel(const float* __restrict__ logits, const float* __restrict__ labels,
            const float* __restrict__ olg, const float* __restrict__ otg) {
    __shared__ float sAcc[145];
    const int tid = threadIdx.x;
    if (tid < 145) sAcc[tid] = 0.f;
    __syncthreads();

    const int T   = 32768;
    const int TPB = T / 16;                 // 2048 rows per block, 16 chunks/batch
    const int b   = blockIdx.y;
    const int t0  = blockIdx.x * TPB;
    const int g   = tid & 3;                // k-pair index: k = 2g, 2g+1
    const int grp = tid >> 2;               // 64 t-groups per block

    const float* lg = logits + (size_t)b * T * 8;
    const float* yb = labels + (size_t)b * T * 8;
    const float* ob = olg + (size_t)b * T;
    const float* tb = otg + (size_t)b * T;

    float A0[8], A1[8], W0[8], W1[8];
#pragma unroll
    for (int n = 0; n < 8; n++) { A0[n] = A1[n] = W0[n] = W1[n] = 0.f; }
    float s10 = 0.f, s11 = 0.f, s20 = 0.f, s21 = 0.f, ov = 0.f;

#pragma unroll 2
    for (int t = t0 + grp; t < t0 + TPB; t += 64) {
        float2 x2 = *reinterpret_cast<const float2*>(lg + t * 8 + 2 * g);
        float4 y0 = *reinterpret_cast<const float4*>(yb + t * 8);
        float4 y1 = *reinterpret_cast<const float4*>(yb + t * 8 + 4);
        float yv[8] = {y0.x, y0.y, y0.z, y0.w, y1.x, y1.y, y1.z, y1.w};
        proc(x2.x, yv, A0, W0, s10, s20);
        proc(x2.y, yv, A1, W1, s11, s21);
        if (g == 0) { float d = ob[t] - tb[t]; ov = fmaf(d, d, ov); }
    }

    // warp-tree reduce across lanes sharing the same g (stride 4,8,16)
#pragma unroll
    for (int off = 16; off >= 4; off >>= 1) {
#pragma unroll
        for (int n = 0; n < 8; n++) {
            A0[n] += __shfl_down_sync(FULLMASK, A0[n], off);
            A1[n] += __shfl_down_sync(FULLMASK, A1[n], off);
            W0[n] += __shfl_down_sync(FULLMASK, W0[n], off);
            W1[n] += __shfl_down_sync(FULLMASK, W1[n], off);
        }
        s10 += __shfl_down_sync(FULLMASK, s10, off);
        s11 += __shfl_down_sync(FULLMASK, s11, off);
        s20 += __shfl_down_sync(FULLMASK, s20, off);
        s21 += __shfl_down_sync(FULLMASK, s21, off);
        ov  += __shfl_down_sync(FULLMASK, ov,  off);
    }

    const int lane = tid & 31;
    if (lane < 4) {                          // lane == g holds the warp sums
        const int k0 = 2 * g, k1 = k0 + 1;
#pragma unroll
        for (int n = 0; n < 8; n++) {
            atomicAdd(&sAcc[k0 * 8 + n], A0[n]);
            atomicAdd(&sAcc[k1 * 8 + n], A1[n]);
            atomicAdd(&sAcc[64 + k0 * 8 + n], W0[n]);
            atomicAdd(&sAcc[64 + k1 * 8 + n], W1[n]);
        }
        atomicAdd(&sAcc[128 + k0], s10);
        atomicAdd(&sAcc[128 + k1], s11);
        atomicAdd(&sAcc[136 + k0], s20);
        atomicAdd(&sAcc[136 + k1], s21);
        if (g == 0) atomicAdd(&sAcc[144], ov);
    }
    __syncthreads();
    if (tid < 144)       atomicAdd(&gBuf[b * 144 + tid], sAcc[tid]);
    else if (tid == 144) atomicAdd(&gBuf[4608 + 0], sAcc[144]);
}

// Per-batch: attractor gram (ortho+contrast) + subset-DP assignment + assign loss
__global__ void __launch_bounds__(256)
batch_kernel(const float* __restrict__ att) {
    __shared__ float rb[36];
    __shared__ float csh[64];
    __shared__ float dp[256];
    __shared__ int   ch[256];
    const int b = blockIdx.x, tid = threadIdx.x;

    if (tid < 36) rb[tid] = 0.f;
    if (tid < 64) {
        int k = tid >> 3;
        float c = (gBuf[b * 144 + 128 + k] + gBuf[b * 144 + tid]) * (1.f / 32768.f);
        if (!(fabsf(c) <= 1e30f)) c = 100.f;   // nan_to_num(cost, 100)
        csh[tid] = c;
    }
    if (tid == 0) dp[0] = 0.f;
    __syncthreads();

    // --- attractor gram: thread = dim d, 8 rows each ---
    const float* ab = att + (size_t)b * 8 * 256;
    float a[8];
#pragma unroll
    for (int k = 0; k < 8; k++) a[k] = ab[k * 256 + tid];
    float cp[36];
    {
        int idx = 0;
#pragma unroll
        for (int k = 0; k < 8; k++)
#pragma unroll
            for (int j = k; j < 8; j++) cp[idx++] = a[k] * a[j];
    }
#pragma unroll
    for (int off = 16; off >= 1; off >>= 1)
#pragma unroll
        for (int i = 0; i < 36; i++) cp[i] += __shfl_down_sync(FULLMASK, cp[i], off);
    if ((tid & 31) == 0)
#pragma unroll
        for (int i = 0; i < 36; i++) atomicAdd(&rb[i], cp[i]);

    // --- subset-DP (exact assignment), mask-parallel, level-synchronous ---
    for (int r = 1; r <= 8; r++) {
        __syncthreads();
        int m = tid;
        if (m >= 1 && __popc(m) == r) {
            float best = 1e30f; int bn = 0;
#pragma unroll
            for (int n = 0; n < 8; n++) {
                if (m & (1 << n)) {
                    float v = dp[m ^ (1 << n)] + csh[(r - 1) * 8 + n];
                    if (v < best) { best = v; bn = n; }
                }
            }
            dp[m] = best; ch[m] = bn;
        }
    }
    __syncthreads();

    if (tid == 0) {
        // gram finalize
        float nrm[8]; int di = 0;
        for (int k = 0; k < 8; k++) { nrm[k] = fmaxf(sqrtf(rb[di]), 1e-12f); di += 8 - k; }
        float ortho = 0.f, contr = 0.f; int idx = 0;
        for (int k = 0; k < 8; k++)
            for (int j = k; j < 8; j++) {
                float s = rb[idx] / (nrm[k] * nrm[j]);
                if (j == k) { float d = s - 1.f; ortho += d * d; }
                else { ortho += 2.f * s * s; contr += 2.f * fmaxf(s + 0.5f, 0.f); }
                idx++;
            }
        atomicAdd(&gBuf[4608 + 2], ortho);
        atomicAdd(&gBuf[4608 + 3], contr);

        // backtrack DP -> col_ind, then assign loss for this batch
        int mask = 255, col[8];
        for (int r = 7; r >= 0; --r) { int n = ch[mask]; col[r] = n; mask ^= (1 << n); }
        float asn = 0.f;
        for (int k = 0; k < 8; k++)
            asn += 0.75f * (gBuf[b * 144 + 136 + k]
                            - 0.8f * gBuf[b * 144 + 64 + k * 8 + col[k]]);
        atomicAdd(&gBuf[4608 + 1], asn);
    }
}

__global__ void __launch_bounds__(256)
final_kernel(const float* __restrict__ exist, float* __restrict__ out, int out_size) {
    __shared__ float sh[9];
    const int tid = threadIdx.x;
    float e  = exist[tid];                       // exactly 256 elements (B*K)
    float ax = fabsf(e);
    float l  = __logf(1.f + __expf(-ax));
    float spn = l + fmaxf(-e, 0.f);              // softplus(-e)
    float spp = l + fmaxf(e, 0.f);               // softplus(e)
    float v   = 4.5f * spn + 0.1f * spp;         // PW*0.9, 0.1
#pragma unroll
    for (int off = 16; off >= 1; off >>= 1) v += __shfl_down_sync(FULLMASK, v, off);
    if ((tid & 31) == 0) sh[tid >> 5] = v;
    __syncthreads();
    if (tid == 0) {
        float es = 0.f;
        for (int i = 0; i < 8; i++) es += sh[i];
        float total = gBuf[4608 + 1] * (1.f / 8388608.f)          // assign mean (B*T*K)
                    + es * (1.f / 256.f)                          // exist mean
                    + 0.1f * gBuf[4608 + 2] * (1.f / 2048.f)      // ortho mean (B*K*K)
                    + 0.1f * gBuf[4608 + 3] * (1.f / 1792.f)      // contrast /(B*K*(K-1))
                    + 0.5f * gBuf[4608 + 0] * (1.f / 1048576.f);  // overlap mean (B*T)
        sh[8] = total;
    }
    __syncthreads();
    float total = sh[8];
    for (int i = tid; i < out_size; i += blockDim.x) out[i] = total;
}

extern "C" void kernel_launch(void* const* d_in, const int* in_sizes, int n_in,
                              void* d_out, int out_size) {
    const float* logits    = (const float*)d_in[0];
    const float* existence = (const float*)d_in[1];
    const float* attract   = (const float*)d_in[2];
    const float* labels    = (const float*)d_in[3];
    const float* olg       = (const float*)d_in[4];
    const float* otg       = (const float*)d_in[5];
    float* out = (float*)d_out;

    zero_kernel<<<10, 512>>>();
    dim3 grid(16, 32);
    main_kernel<<<grid, 256>>>(logits, labels, olg, otg);
    batch_kernel<<<32, 256>>>(attract);
    final_kernel<<<1, 256>>>(existence, out, out_size);
}

// round 2
// speedup vs baseline: 1.6423x; 1.6423x over previous
#include <cuda_runtime.h>
#include <cuda_bf16.h>
#include <cstddef>

// B=32, T=32768, K=N=8, D=256
// EPS=0.1, PW=5, GAMMA=2, ALPHA=0.25, MARGIN=0.5
// weights: exist 1.0, ortho 0.1, contr 0.1, overlap 0.5
//
// Decomposition (one pass over logits/labels):
//   nlp = softplus(-x); p2 = sigmoid(x)^2
//   S1[k] = sum_t (nlp + x)                 -> cost[k][n] = (S1[k] + A[k][n])/T
//   A[k][n] = sum_t ((PW-1)*nlp - x)*y[n]
//   S2[k] = sum_t p2*(nlp + 0.9x)           -> assign[k] = 0.75*(S2[k] - 0.8*W[k][col_k])
//   W[k][n] = sum_t p2*x*y[n]

#define FULLMASK 0xffffffffu

#define CHUNKS 13
#define ROWS_PER_CHUNK 2521    // ceil(32768/13)
#define SLOT 145               // 64 A + 64 W + 8 S1 + 8 S2 + 1 overlap

__device__ float gPart[32 * CHUNKS * SLOT];   // per-(batch,chunk) partials
__device__ float gOut[32 * 5];                // per-batch: assign, ortho, contr, overlap, exist

__device__ __forceinline__ void proc(float x, const float* yv,
                                     float* A, float* W, float& s1, float& s2) {
    float ax  = fabsf(x);
    float e   = __expf(-ax);
    float l   = __logf(1.f + e);
    float nlp = l + fmaxf(-x, 0.f);         // softplus(-x) = -log sigmoid(x)
    float p2  = __expf(-2.f * nlp);         // sigmoid(x)^2
    float u   = fmaf(4.f, nlp, -x);         // (PW-1)*nlp - x
    float w   = p2 * x;
    s1 += nlp + x;
    s2  = fmaf(p2, fmaf(0.9f, x, nlp), s2);
#pragma unroll
    for (int n = 0; n < 8; n++) {
        A[n] = fmaf(yv[n], u, A[n]);
        W[n] = fmaf(yv[n], w, W[n]);
    }
}

__global__ void __launch_bounds__(256, 3)
main_kernel(const float* __restrict__ logits, const float* __restrict__ labels,
            const float* __restrict__ olg, const float* __restrict__ otg) {
    __shared__ float sAcc[SLOT];
    const int tid = threadIdx.x;
    if (tid < SLOT) sAcc[tid] = 0.f;
    __syncthreads();

    const int T    = 32768;
    const int c    = blockIdx.x;            // chunk 0..12
    const int b    = blockIdx.y;            // batch
    const int t0   = c * ROWS_PER_CHUNK;
    const int tend = min(t0 + ROWS_PER_CHUNK, T);
    const int g    = tid & 3;               // k-pair: k = 2g, 2g+1
    const int grp  = tid >> 2;              // 64 row-groups per block

    const float* lg = logits + (size_t)b * T * 8;
    const float* yb = labels + (size_t)b * T * 8;
    const float* ob = olg + (size_t)b * T;
    const float* tb = otg + (size_t)b * T;

    // ---- overlap MSE prologue: coalesced, all 256 threads ----
    float ov = 0.f;
    for (int i = t0 + tid; i < tend; i += 256) {
        float d = ob[i] - tb[i];
        ov = fmaf(d, d, ov);
    }

    // ---- main streaming pass ----
    float A0[8], A1[8], W0[8], W1[8];
#pragma unroll
    for (int n = 0; n < 8; n++) { A0[n] = A1[n] = W0[n] = W1[n] = 0.f; }
    float s10 = 0.f, s11 = 0.f, s20 = 0.f, s21 = 0.f;

#pragma unroll 2
    for (int t = t0 + grp; t < tend; t += 64) {
        float2 x2 = *reinterpret_cast<const float2*>(lg + t * 8 + 2 * g);
        float4 y0 = *reinterpret_cast<const float4*>(yb + t * 8);
        float4 y1 = *reinterpret_cast<const float4*>(yb + t * 8 + 4);
        float yv[8] = {y0.x, y0.y, y0.z, y0.w, y1.x, y1.y, y1.z, y1.w};
        proc(x2.x, yv, A0, W0, s10, s20);
        proc(x2.y, yv, A1, W1, s11, s21);
    }

    // warp-tree reduce across lanes sharing the same g (stride 4,8,16)
#pragma unroll
    for (int off = 16; off >= 4; off >>= 1) {
#pragma unroll
        for (int n = 0; n < 8; n++) {
            A0[n] += __shfl_down_sync(FULLMASK, A0[n], off);
            A1[n] += __shfl_down_sync(FULLMASK, A1[n], off);
            W0[n] += __shfl_down_sync(FULLMASK, W0[n], off);
            W1[n] += __shfl_down_sync(FULLMASK, W1[n], off);
        }
        s10 += __shfl_down_sync(FULLMASK, s10, off);
        s11 += __shfl_down_sync(FULLMASK, s11, off);
        s20 += __shfl_down_sync(FULLMASK, s20, off);
        s21 += __shfl_down_sync(FULLMASK, s21, off);
    }
    // overlap: full-warp tree
#pragma unroll
    for (int off = 16; off >= 1; off >>= 1) ov += __shfl_down_sync(FULLMASK, ov, off);

    const int lane = tid & 31;
    if (lane < 4) {
        const int k0 = 2 * g, k1 = k0 + 1;
#pragma unroll
        for (int n = 0; n < 8; n++) {
            atomicAdd(&sAcc[k0 * 8 + n], A0[n]);
            atomicAdd(&sAcc[k1 * 8 + n], A1[n]);
            atomicAdd(&sAcc[64 + k0 * 8 + n], W0[n]);
            atomicAdd(&sAcc[64 + k1 * 8 + n], W1[n]);
        }
        atomicAdd(&sAcc[128 + k0], s10);
        atomicAdd(&sAcc[128 + k1], s11);
        atomicAdd(&sAcc[136 + k0], s20);
        atomicAdd(&sAcc[136 + k1], s21);
    }
    if (lane == 0) atomicAdd(&sAcc[144], ov);
    __syncthreads();

    if (tid < SLOT) gPart[(b * CHUNKS + c) * SLOT + tid] = sAcc[tid];
}

// Per-batch: chunk reduction + attractor gram + subset-DP assignment + existence row
__global__ void __launch_bounds__(256)
batch_kernel(const float* __restrict__ att, const float* __restrict__ exist) {
    __shared__ float red[SLOT];
    __shared__ float rb[37];        // 36 gram upper-tri + [36] existence sum
    __shared__ float csh[64];
    __shared__ float dp[256];
    __shared__ int   ch[256];
    const int b = blockIdx.x, tid = threadIdx.x;

    // reduce 13 chunk partials (independent loads -> good MLP)
    if (tid < SLOT) {
        float s = 0.f;
#pragma unroll
        for (int c = 0; c < CHUNKS; c++) s += gPart[(b * CHUNKS + c) * SLOT + tid];
        red[tid] = s;
    }
    if (tid < 37) rb[tid] = 0.f;
    if (tid == 0) dp[0] = 0.f;
    __syncthreads();

    if (tid < 64) {
        int k = tid >> 3;
        float c = (red[128 + k] + red[tid]) * (1.f / 32768.f);
        if (!(fabsf(c) <= 1e30f)) c = 100.f;
        csh[tid] = c;
    }

    // existence BCE for this batch's 8 logits
    if (tid < 8) {
        float e  = exist[b * 8 + tid];
        float l  = __logf(1.f + __expf(-fabsf(e)));
        float spn = l + fmaxf(-e, 0.f);
        float spp = l + fmaxf(e, 0.f);
        atomicAdd(&rb[36], 4.5f * spn + 0.1f * spp);
    }

    // attractor gram: thread = dim d
    const float* ab = att + (size_t)b * 8 * 256;
    float a[8];
#pragma unroll
    for (int k = 0; k < 8; k++) a[k] = ab[k * 256 + tid];
    float cp[36];
    {
        int idx = 0;
#pragma unroll
        for (int k = 0; k < 8; k++)
#pragma unroll
            for (int j = k; j < 8; j++) cp[idx++] = a[k] * a[j];
    }
#pragma unroll
    for (int off = 16; off >= 1; off >>= 1)
#pragma unroll
        for (int i = 0; i < 36; i++) cp[i] += __shfl_down_sync(FULLMASK, cp[i], off);
    if ((tid & 31) == 0)
#pragma unroll
        for (int i = 0; i < 36; i++) atomicAdd(&rb[i], cp[i]);

    // subset-DP exact assignment (level-synchronous over popcount)
    for (int r = 1; r <= 8; r++) {
        __syncthreads();
        int m = tid;
        if (m >= 1 && m < 256 && __popc(m) == r) {
            float best = 1e30f; int bn = 0;
#pragma unroll
            for (int n = 0; n < 8; n++) {
                if (m & (1 << n)) {
                    float v = dp[m ^ (1 << n)] + csh[(r - 1) * 8 + n];
                    if (v < best) { best = v; bn = n; }
                }
            }
            dp[m] = best; ch[m] = bn;
        }
    }
    __syncthreads();

    if (tid == 0) {
        // gram finalize
        float nrm[8]; int di = 0;
        for (int k = 0; k < 8; k++) { nrm[k] = fmaxf(sqrtf(rb[di]), 1e-12f); di += 8 - k; }
        float ortho = 0.f, contr = 0.f; int idx = 0;
        for (int k = 0; k < 8; k++)
            for (int j = k; j < 8; j++) {
                float s = rb[idx] / (nrm[k] * nrm[j]);
                if (j == k) { float d = s - 1.f; ortho += d * d; }
                else { ortho += 2.f * s * s; contr += 2.f * fmaxf(s + 0.5f, 0.f); }
                idx++;
            }

        // backtrack DP -> col_ind -> assign loss
        int mask = 255, col[8];
        for (int r = 7; r >= 0; --r) { int n = ch[mask]; col[r] = n; mask ^= (1 << n); }
        float asn = 0.f;
        for (int k = 0; k < 8; k++)
            asn += 0.75f * (red[136 + k] - 0.8f * red[64 + k * 8 + col[k]]);

        gOut[b * 5 + 0] = asn;
        gOut[b * 5 + 1] = ortho;
        gOut[b * 5 + 2] = contr;
        gOut[b * 5 + 3] = red[144];   // overlap partial
        gOut[b * 5 + 4] = rb[36];     // existence partial
    }
}

__global__ void __launch_bounds__(256)
final_kernel(float* __restrict__ out, int out_size) {
    __shared__ float sv[192];
    __shared__ float tot;
    const int tid = threadIdx.x;
    sv[tid < 192 ? tid : 0] = 0.f;          // init
    __syncthreads();
    if (tid < 160) sv[tid] = gOut[tid];     // parallel loads, one round trip
    __syncthreads();
    if (tid < 5) {
        float s = 0.f;
#pragma unroll
        for (int bb = 0; bb < 32; bb++) s += sv[bb * 5 + tid];
        sv[160 + tid] = s;
    }
    __syncthreads();
    if (tid == 0) {
        tot = sv[160 + 0] * (1.f / 8388608.f)          // assign mean (B*T*K)
            + sv[160 + 4] * (1.f / 256.f)              // exist mean
            + 0.1f * sv[160 + 1] * (1.f / 2048.f)      // ortho mean (B*K*K)
            + 0.1f * sv[160 + 2] * (1.f / 1792.f)      // contrast /(B*K*(K-1))
            + 0.5f * sv[160 + 3] * (1.f / 1048576.f);  // overlap mean (B*T)
    }
    __syncthreads();
    float t = tot;
    for (int i = tid; i < out_size; i += blockDim.x) out[i] = t;
}

extern "C" void kernel_launch(void* const* d_in, const int* in_sizes, int n_in,
                              void* d_out, int out_size) {
    const float* logits    = (const float*)d_in[0];
    const float* existence = (const float*)d_in[1];
    const float* attract   = (const float*)d_in[2];
    const float* labels    = (const float*)d_in[3];
    const float* olg       = (const float*)d_in[4];
    const float* otg       = (const float*)d_in[5];
    float* out = (float*)d_out;

    dim3 grid(CHUNKS, 32);
    main_kernel<<<grid, 256>>>(logits, labels, olg, otg);
    batch_kernel<<<32, 256>>>(attract, existence);
    final_kernel<<<1, 256>>>(out, out_size);
}

// round 3
// speedup vs baseline: 2.0558x; 1.2518x over previous
#include <cuda_runtime.h>
#include <cuda_bf16.h>
#include <cstddef>

// B=32, T=32768, K=N=8, D=256
// Decomposition (one pass):
//   nlp = softplus(-x); p2 = sigmoid(x)^2
//   u = 4*nlp - x ; w = p2*x
//   A[k][n] = sum u*y ; W[k][n] = sum w*y   (via mma.m16n8k16, u/w rows stacked)
//   S1[k] = sum (nlp+x) ; S2[k] = sum p2*(nlp+0.9x)
//   cost = (S1+A)/T ; assign_k = 0.75*(S2[k] - 0.8*W[k][col_k])

#define FULLMASK 0xffffffffu
#define CHUNKS 16
#define TPB_T 2048
#define SLOT 145   // 64 A + 64 W + 8 S1 + 8 S2 + 1 overlap

__device__ float gPart[32 * CHUNKS * SLOT];
__device__ float gTotal;
__device__ unsigned gCount;

__device__ __forceinline__ unsigned pk(float hi, float lo) {
    unsigned r;
    asm("cvt.rn.bf16x2.f32 %0, %1, %2;" : "=r"(r) : "f"(hi), "f"(lo));
    return r;
}

__device__ __forceinline__ void procE(float x, float& u, float& w,
                                      float& s1, float& s2) {
    float e = __expf(-x);
    float tt = 1.f + e;
    float nlp = __logf(tt);
    float r;
    asm("rcp.approx.ftz.f32 %0, %1;" : "=f"(r) : "f"(tt));
    float p2 = r * r;                     // sigmoid(x)^2
    u = fmaf(4.f, nlp, -x);
    w = p2 * x;
    s1 += nlp + x;
    s2 = fmaf(p2, fmaf(0.9f, x, nlp), s2);
}

__global__ void __launch_bounds__(256, 4)
main_kernel(const float* __restrict__ logits, const float* __restrict__ labels,
            const float* __restrict__ olg, const float* __restrict__ otg) {
    __shared__ float sAcc[SLOT];
    const int tid = threadIdx.x;
    if (tid < SLOT) sAcc[tid] = 0.f;
    if (blockIdx.x == 0 && blockIdx.y == 0 && tid == 0) { gTotal = 0.f; gCount = 0u; }
    __syncthreads();

    const int b = blockIdx.y, c = blockIdx.x;
    const int t0 = c * TPB_T;
    const float* lg = logits + (size_t)b * 32768 * 8;
    const float* yb = labels + (size_t)b * 32768 * 8;

    // ---- overlap MSE (coalesced float4) ----
    const float* ob = olg + (size_t)b * 32768 + t0;
    const float* tb = otg + (size_t)b * 32768 + t0;
    float ov = 0.f;
    for (int i = tid; i < TPB_T / 4; i += 256) {
        float4 o4 = reinterpret_cast<const float4*>(ob)[i];
        float4 t4 = reinterpret_cast<const float4*>(tb)[i];
        float d0 = o4.x - t4.x, d1 = o4.y - t4.y;
        float d2 = o4.z - t4.z, d3 = o4.w - t4.w;
        ov = fmaf(d0, d0, fmaf(d1, d1, fmaf(d2, d2, fmaf(d3, d3, ov))));
    }

    // ---- main mma loop: warp covers 256 t's as 16 steps of 16 ----
    const int wrp = tid >> 5, l = tid & 31;
    const int gid = l >> 2, tg = l & 3;
    const int tw = t0 + wrp * 256;
    const float* xp = lg + (size_t)tw * 8 + gid;
    const float* yp = yb + (size_t)tw * 8 + gid;
    const int o0 = 16 * tg, o1 = o0 + 8, o2 = o0 + 64, o3 = o0 + 72;

    float c0 = 0.f, c1 = 0.f, c2 = 0.f, c3 = 0.f, s1 = 0.f, s2 = 0.f;

#pragma unroll 4
    for (int i = 0; i < 16; i++) {
        const int base = i * 128;
        float x0 = xp[base + o0], x1 = xp[base + o1];
        float x2 = xp[base + o2], x3 = xp[base + o3];
        float y0 = yp[base + o0], y1 = yp[base + o1];
        float y2 = yp[base + o2], y3 = yp[base + o3];
        float u0, u1, u2, u3, w0, w1, w2, w3;
        procE(x0, u0, w0, s1, s2);
        procE(x1, u1, w1, s1, s2);
        procE(x2, u2, w2, s1, s2);
        procE(x3, u3, w3, s1, s2);
        unsigned a0 = pk(u1, u0), a1 = pk(w1, w0);
        unsigned a2 = pk(u3, u2), a3 = pk(w3, w2);
        unsigned b0 = pk(y1, y0), b1 = pk(y3, y2);
        asm("mma.sync.aligned.m16n8k16.row.col.f32.bf16.bf16.f32 "
            "{%0,%1,%2,%3}, {%4,%5,%6,%7}, {%8,%9}, {%0,%1,%2,%3};"
            : "+f"(c0), "+f"(c1), "+f"(c2), "+f"(c3)
            : "r"(a0), "r"(a1), "r"(a2), "r"(a3), "r"(b0), "r"(b1));
    }

    // s1/s2: reduce across the 4 lanes of each gid group
    s1 += __shfl_xor_sync(FULLMASK, s1, 1);
    s1 += __shfl_xor_sync(FULLMASK, s1, 2);
    s2 += __shfl_xor_sync(FULLMASK, s2, 1);
    s2 += __shfl_xor_sync(FULLMASK, s2, 2);
#pragma unroll
    for (int off = 16; off >= 1; off >>= 1) ov += __shfl_down_sync(FULLMASK, ov, off);

    // C frag: c0=(gid,2tg) c1=(gid,2tg+1) rows 0-7 = A ; c2,c3 rows 8-15 = W
    atomicAdd(&sAcc[gid * 8 + 2 * tg],          c0);
    atomicAdd(&sAcc[gid * 8 + 2 * tg + 1],      c1);
    atomicAdd(&sAcc[64 + gid * 8 + 2 * tg],     c2);
    atomicAdd(&sAcc[64 + gid * 8 + 2 * tg + 1], c3);
    if (tg == 0) {
        atomicAdd(&sAcc[128 + gid], s1);
        atomicAdd(&sAcc[136 + gid], s2);
    }
    if (l == 0) atomicAdd(&sAcc[144], ov);
    __syncthreads();

    if (tid < SLOT) gPart[(b * CHUNKS + c) * SLOT + tid] = sAcc[tid];
}

// Per-batch: chunk reduce + gram + subset-DP assignment + existence; last block
// folds everything into the scalar output.
__global__ void __launch_bounds__(256)
batch_kernel(const float* __restrict__ att, const float* __restrict__ exist,
             float* __restrict__ out, int out_size) {
    __shared__ float red[SLOT];
    __shared__ float rb[37];     // 36 gram upper-tri + [36] existence sum
    __shared__ float csh[64];
    __shared__ float dp[256];
    __shared__ int   ch[256];
    __shared__ int   sLast;
    __shared__ float sTot;
    const int b = blockIdx.x, tid = threadIdx.x;

    if (tid < SLOT) {
        float s = 0.f;
#pragma unroll
        for (int c = 0; c < CHUNKS; c++) s += gPart[(b * CHUNKS + c) * SLOT + tid];
        red[tid] = s;
    }
    if (tid < 37) rb[tid] = 0.f;
    if (tid == 0) { dp[0] = 0.f; sLast = 0; }
    __syncthreads();

    if (tid < 64) {
        int k = tid >> 3;
        float cc = (red[128 + k] + red[tid]) * (1.f / 32768.f);
        if (!(fabsf(cc) <= 1e30f)) cc = 100.f;
        csh[tid] = cc;
    }
    if (tid < 8) {
        float e  = exist[b * 8 + tid];
        float ll = __logf(1.f + __expf(-fabsf(e)));
        float spn = ll + fmaxf(-e, 0.f);
        float spp = ll + fmaxf(e, 0.f);
        atomicAdd(&rb[36], 4.5f * spn + 0.1f * spp);
    }

    // attractor gram: thread = dim d (256 dims)
    const float* ab = att + (size_t)b * 8 * 256;
    float a[8];
#pragma unroll
    for (int k = 0; k < 8; k++) a[k] = ab[k * 256 + tid];
    float cp[36];
    {
        int idx = 0;
#pragma unroll
        for (int k = 0; k < 8; k++)
#pragma unroll
            for (int j = k; j < 8; j++) cp[idx++] = a[k] * a[j];
    }
#pragma unroll
    for (int off = 16; off >= 1; off >>= 1)
#pragma unroll
        for (int i = 0; i < 36; i++) cp[i] += __shfl_down_sync(FULLMASK, cp[i], off);
    if ((tid & 31) == 0)
#pragma unroll
        for (int i = 0; i < 36; i++) atomicAdd(&rb[i], cp[i]);

    // subset-DP exact assignment
    for (int r = 1; r <= 8; r++) {
        __syncthreads();
        int m = tid;
        if (m >= 1 && m < 256 && __popc(m) == r) {
            float best = 1e30f; int bn = 0;
#pragma unroll
            for (int n = 0; n < 8; n++) {
                if (m & (1 << n)) {
                    float v = dp[m ^ (1 << n)] + csh[(r - 1) * 8 + n];
                    if (v < best) { best = v; bn = n; }
                }
            }
            dp[m] = best; ch[m] = bn;
        }
    }
    __syncthreads();

    if (tid == 0) {
        float nrm[8]; int di = 0;
        for (int k = 0; k < 8; k++) { nrm[k] = fmaxf(sqrtf(rb[di]), 1e-12f); di += 8 - k; }
        float ortho = 0.f, contr = 0.f; int idx = 0;
        for (int k = 0; k < 8; k++)
            for (int j = k; j < 8; j++) {
                float s = rb[idx] / (nrm[k] * nrm[j]);
                if (j == k) { float d = s - 1.f; ortho += d * d; }
                else { ortho += 2.f * s * s; contr += 2.f * fmaxf(s + 0.5f, 0.f); }
                idx++;
            }

        int mask = 255, col[8];
        for (int r = 7; r >= 0; --r) { int n = ch[mask]; col[r] = n; mask ^= (1 << n); }
        float asn = 0.f;
        for (int k = 0; k < 8; k++)
            asn += 0.75f * (red[136 + k] - 0.8f * red[64 + k * 8 + col[k]]);

        float contrib = asn * (1.f / 8388608.f)          // assign mean (B*T*K)
                      + rb[36] * (1.f / 256.f)           // exist mean
                      + 0.1f * ortho * (1.f / 2048.f)    // ortho mean
                      + 0.1f * contr * (1.f / 1792.f)    // contrast
                      + 0.5f * red[144] * (1.f / 1048576.f); // overlap mean
        atomicAdd(&gTotal, contrib);
        __threadfence();
        unsigned old = atomicAdd(&gCount, 1u);
        if (old == 31u) { sLast = 1; sTot = atomicAdd(&gTotal, 0.f); }
    }
    __syncthreads();
    if (sLast) {
        float t = sTot;
        for (int i = tid; i < out_size; i += blockDim.x) out[i] = t;
    }
}

extern "C" void kernel_launch(void* const* d_in, const int* in_sizes, int n_in,
                              void* d_out, int out_size) {
    const float* logits    = (const float*)d_in[0];
    const float* existence = (const float*)d_in[1];
    const float* attract   = (const float*)d_in[2];
    const float* labels    = (const float*)d_in[3];
    const float* olg       = (const float*)d_in[4];
    const float* otg       = (const float*)d_in[5];
    float* out = (float*)d_out;

    dim3 grid(CHUNKS, 32);
    main_kernel<<<grid, 256>>>(logits, labels, olg, otg);
    batch_kernel<<<32, 256>>>(attract, existence, out, out_size);
}